// round 10
// baseline (speedup 1.0000x reference)
#include <cuda_runtime.h>

// BYOL loss: out = 2 - 2 * mean_i( dot(x_i, xt_i) / (max(||x_i||,eps)*max(||xt_i||,eps)) )
// R1's proven streaming shape (1 row per 128-thread block, 1 float4/thread/input)
// + fused last-block-retires reduction (no second launch).

#define N_ROWS 8192
#define D_DIM  512
#define EPS 1e-8f

#define NTHREADS 128

__device__ float g_partial[N_ROWS];
__device__ unsigned int g_count = 0;

__global__ void __launch_bounds__(NTHREADS) byol_kernel(
    const float* __restrict__ x, const float* __restrict__ xt,
    float* __restrict__ out)
{
    const int row = blockIdx.x;
    const int t = threadIdx.x;
    const int lane = t & 31;
    const int warp = t >> 5;

    // ---- per-row cosine (128 threads x 1 float4 per input) ----
    const float4* a4 = reinterpret_cast<const float4*>(x  + (size_t)row * D_DIM);
    const float4* b4 = reinterpret_cast<const float4*>(xt + (size_t)row * D_DIM);

    float4 av = a4[t];
    float4 bv = b4[t];

    float dot = av.x*bv.x + av.y*bv.y + av.z*bv.z + av.w*bv.w;
    float aa  = av.x*av.x + av.y*av.y + av.z*av.z + av.w*av.w;
    float bb  = bv.x*bv.x + bv.y*bv.y + bv.z*bv.z + bv.w*bv.w;

    #pragma unroll
    for (int off = 16; off > 0; off >>= 1) {
        dot += __shfl_xor_sync(0xFFFFFFFFu, dot, off);
        aa  += __shfl_xor_sync(0xFFFFFFFFu, aa,  off);
        bb  += __shfl_xor_sync(0xFFFFFFFFu, bb,  off);
    }

    __shared__ float sd[4], sa[4], sb[4];
    if (lane == 0) { sd[warp] = dot; sa[warp] = aa; sb[warp] = bb; }
    __syncthreads();

    __shared__ bool s_last;
    if (t == 0) {
        float Dd = sd[0] + sd[1] + sd[2] + sd[3];
        float Aa = sa[0] + sa[1] + sa[2] + sa[3];
        float Bb = sb[0] + sb[1] + sb[2] + sb[3];
        float na = fmaxf(sqrtf(Aa), EPS);
        float nb = fmaxf(sqrtf(Bb), EPS);
        g_partial[row] = Dd / (na * nb);
        __threadfence();
        // wraps to 0 at N_ROWS-1 -> counter self-resets for each graph replay
        unsigned int old = atomicInc(&g_count, N_ROWS - 1);
        s_last = (old == N_ROWS - 1);
    }
    __syncthreads();

    if (!s_last) return;

    // ---- last block: deterministic reduce of 8192 partials (L2-resident) ----
    // 64 values per thread; 8 independent accumulators -> 8 loads in flight.
    float acc[8];
    #pragma unroll
    for (int j = 0; j < 8; j++) acc[j] = 0.0f;

    #pragma unroll
    for (int i = 0; i < 64; i += 8) {
        #pragma unroll
        for (int j = 0; j < 8; j++)
            acc[j] += g_partial[t + (i + j) * NTHREADS];
    }
    float s = ((acc[0] + acc[1]) + (acc[2] + acc[3]))
            + ((acc[4] + acc[5]) + (acc[6] + acc[7]));

    #pragma unroll
    for (int off = 16; off > 0; off >>= 1)
        s += __shfl_xor_sync(0xFFFFFFFFu, s, off);

    __shared__ float s_w[4];
    if (lane == 0) s_w[warp] = s;
    __syncthreads();

    if (t == 0) {
        float v = (s_w[0] + s_w[1]) + (s_w[2] + s_w[3]);
        out[0] = 2.0f - 2.0f * (v / (float)N_ROWS);
    }
}

extern "C" void kernel_launch(void* const* d_in, const int* in_sizes, int n_in,
                              void* d_out, int out_size)
{
    const float* x  = (const float*)d_in[0];
    const float* xt = (const float*)d_in[1];
    float* out = (float*)d_out;

    byol_kernel<<<N_ROWS, NTHREADS>>>(x, xt, out);
}

// round 13
// speedup vs baseline: 1.1662x; 1.1662x over previous
#include <cuda_runtime.h>

// BYOL loss: out = 2 - 2 * mean_i( dot(x_i, xt_i) / (max(||x_i||,eps)*max(||xt_i||,eps)) )
// R1 streaming shape (1 row per 128-thread block) + single packed integer
// atomicAdd per block: bits[48+] = completion count, bits[0:48) = fixed-point
// sum of (cos+1)*2^30. Integer adds are order-invariant -> deterministic,
// and the atomic return value replaces any threadfence/partials machinery.

#define N_ROWS 8192
#define D_DIM  512
#define EPS 1e-8f

#define NTHREADS 128
#define FIX_SCALE 1073741824.0f   // 2^30
#define COUNT_ONE (1ULL << 48)

__device__ unsigned long long g_accum = 0ULL;

__global__ void __launch_bounds__(NTHREADS) byol_kernel(
    const float* __restrict__ x, const float* __restrict__ xt,
    float* __restrict__ out)
{
    const int row = blockIdx.x;
    const int t = threadIdx.x;
    const int lane = t & 31;
    const int warp = t >> 5;

    // ---- per-row cosine (128 threads x 1 float4 per input) ----
    const float4* a4 = reinterpret_cast<const float4*>(x  + (size_t)row * D_DIM);
    const float4* b4 = reinterpret_cast<const float4*>(xt + (size_t)row * D_DIM);

    float4 av = a4[t];
    float4 bv = b4[t];

    float dot = av.x*bv.x + av.y*bv.y + av.z*bv.z + av.w*bv.w;
    float aa  = av.x*av.x + av.y*av.y + av.z*av.z + av.w*av.w;
    float bb  = bv.x*bv.x + bv.y*bv.y + bv.z*bv.z + bv.w*bv.w;

    #pragma unroll
    for (int off = 16; off > 0; off >>= 1) {
        dot += __shfl_xor_sync(0xFFFFFFFFu, dot, off);
        aa  += __shfl_xor_sync(0xFFFFFFFFu, aa,  off);
        bb  += __shfl_xor_sync(0xFFFFFFFFu, bb,  off);
    }

    __shared__ float sd[4], sa[4], sb[4];
    if (lane == 0) { sd[warp] = dot; sa[warp] = aa; sb[warp] = bb; }
    __syncthreads();

    if (t == 0) {
        float Dd = sd[0] + sd[1] + sd[2] + sd[3];
        float Aa = sa[0] + sa[1] + sa[2] + sa[3];
        float Bb = sb[0] + sb[1] + sb[2] + sb[3];
        float na = fmaxf(sqrtf(Aa), EPS);
        float nb = fmaxf(sqrtf(Bb), EPS);
        float cosv = Dd / (na * nb);

        // fixed-point encode: (cos+1) in [0,2] -> [0, 2^31]; sum <= 2^44 < 2^48
        unsigned long long fx =
            (unsigned long long)llrintf((cosv + 1.0f) * FIX_SCALE);
        unsigned long long contrib = COUNT_ONE + fx;

        unsigned long long old = atomicAdd(&g_accum, contrib);

        if ((old >> 48) == (unsigned long long)(N_ROWS - 1)) {
            // we are the last block; total is old + our contribution
            unsigned long long total = old + contrib;
            unsigned long long sum_fx = total & (COUNT_ONE - 1ULL);
            // mean(cos) = sum_fx / (2^30 * N) - 1
            double mean_cos = (double)sum_fx / ((double)FIX_SCALE * (double)N_ROWS) - 1.0;
            out[0] = (float)(2.0 - 2.0 * mean_cos);
            // reset for next graph replay (no other block touches g_accum now)
            g_accum = 0ULL;
        }
    }
}

extern "C" void kernel_launch(void* const* d_in, const int* in_sizes, int n_in,
                              void* d_out, int out_size)
{
    const float* x  = (const float*)d_in[0];
    const float* xt = (const float*)d_in[1];
    float* out = (float*)d_out;

    byol_kernel<<<N_ROWS, NTHREADS>>>(x, xt, out);
}

// round 16
// speedup vs baseline: 1.6536x; 1.4179x over previous
#include <cuda_runtime.h>

// BYOL loss: out = 2 - 2 * mean_i( dot(x_i, xt_i) / (max(||x_i||,eps)*max(||xt_i||,eps)) )
// R3's proven streaming shape (grid 1024 x 256, warp-per-row, 8 LDG.128/thread)
// with the tail replaced by ONE packed u64 atomicAdd per block:
//   bits[48+] = completion count, bits[0:48) = fixed-point sum of (p_block + 16)*2^26.
// Integer adds are order-invariant -> bit-deterministic; the atomic return value
// carries the full sum, so no threadfence / partials array / re-read phase.

#define N_ROWS 8192
#define D_DIM  512
#define EPS 1e-8f

#define NTHREADS 256
#define WARPS_PER_BLOCK 8
#define NBLOCKS (N_ROWS / WARPS_PER_BLOCK)   // 1024

#define FIX_SCALE 67108864.0f                // 2^26
#define BLOCK_OFFSET 16.0f                   // p_block in [-8,8] -> [8,24]
#define COUNT_ONE (1ULL << 48)

__device__ unsigned long long g_accum = 0ULL;

__global__ void __launch_bounds__(NTHREADS) byol_fused_kernel(
    const float* __restrict__ x, const float* __restrict__ xt,
    float* __restrict__ out)
{
    const int t = threadIdx.x;
    const int lane = t & 31;
    const int warp = t >> 5;                 // 0..7
    const int row = blockIdx.x * WARPS_PER_BLOCK + warp;

    // ---- per-row cosine (one warp per row, 4 float4 per input per lane) ----
    const float4* a4 = reinterpret_cast<const float4*>(x  + (size_t)row * D_DIM);
    const float4* b4 = reinterpret_cast<const float4*>(xt + (size_t)row * D_DIM);

    float4 av[4], bv[4];
    #pragma unroll
    for (int i = 0; i < 4; i++) av[i] = a4[lane + 32 * i];
    #pragma unroll
    for (int i = 0; i < 4; i++) bv[i] = b4[lane + 32 * i];

    float dot = 0.f, aa = 0.f, bb = 0.f;
    #pragma unroll
    for (int i = 0; i < 4; i++) {
        float4 a = av[i], b = bv[i];
        dot += a.x*b.x + a.y*b.y + a.z*b.z + a.w*b.w;
        aa  += a.x*a.x + a.y*a.y + a.z*a.z + a.w*a.w;
        bb  += b.x*b.x + b.y*b.y + b.z*b.z + b.w*b.w;
    }

    #pragma unroll
    for (int off = 16; off > 0; off >>= 1) {
        dot += __shfl_xor_sync(0xFFFFFFFFu, dot, off);
        aa  += __shfl_xor_sync(0xFFFFFFFFu, aa,  off);
        bb  += __shfl_xor_sync(0xFFFFFFFFu, bb,  off);
    }

    __shared__ float s_cos[WARPS_PER_BLOCK];
    if (lane == 0) {
        float na = fmaxf(sqrtf(aa), EPS);
        float nb = fmaxf(sqrtf(bb), EPS);
        s_cos[warp] = dot / (na * nb);
    }
    __syncthreads();

    if (t == 0) {
        float p = ((s_cos[0] + s_cos[1]) + (s_cos[2] + s_cos[3]))
                + ((s_cos[4] + s_cos[5]) + (s_cos[6] + s_cos[7]));

        // fixed-point encode; per-block value < 24*2^26 < 2^31, sum < 2^41 < 2^48
        unsigned long long q =
            (unsigned long long)llrintf((p + BLOCK_OFFSET) * FIX_SCALE);
        unsigned long long contrib = COUNT_ONE + q;

        unsigned long long old = atomicAdd(&g_accum, contrib);

        if ((old >> 48) == (unsigned long long)(NBLOCKS - 1)) {
            unsigned long long total = old + contrib;
            unsigned long long sum_q = total & (COUNT_ONE - 1ULL);
            // sum_p = sum_q / 2^26 - 16*NBLOCKS ; mean_cos = sum_p / N_ROWS
            double sum_p = (double)sum_q / (double)FIX_SCALE
                         - (double)BLOCK_OFFSET * (double)NBLOCKS;
            double mean_cos = sum_p / (double)N_ROWS;
            out[0] = (float)(2.0 - 2.0 * mean_cos);
            // all counts arrived -> no other block touches g_accum; reset for replay
            g_accum = 0ULL;
        }
    }
}

extern "C" void kernel_launch(void* const* d_in, const int* in_sizes, int n_in,
                              void* d_out, int out_size)
{
    const float* x  = (const float*)d_in[0];
    const float* xt = (const float*)d_in[1];
    float* out = (float*)d_out;

    byol_fused_kernel<<<NBLOCKS, NTHREADS>>>(x, xt, out);
}